// round 1
// baseline (speedup 1.0000x reference)
#include <cuda_runtime.h>

// P2V: out[b,vox] = top2-margin of softmax_n( |s2| * exp(-|s1| * |xyz[b,:,n]-grid[:,vox]|^2) )
//
// margin = (exp(v0) - exp(v1)) / sum_n exp(v_n),  v_n = |s2|*exp(-|s1|*dist_n) in (0, s2]
//
// Single pass per output: track top-2 of E(v_n) and sum E(v_n).
// First exp via MUFU ex2 with all constants folded:
//   v = w * 2^( p_n + kX0*g0 + kX1*g1 + kX2*g2 ),
//   kXc = 2*s1*log2e*x_c,  p_n = -s1*log2e*|x_n|^2  (precomputed per (b,n)),
//   w   = s2 * 2^(-s1*log2e*|g|^2)                  (per voxel).
// Second exp (softmax sum) via degree-7 Taylor poly on [0,1] in packed f32x2.

typedef unsigned long long u64;

#define VOXN 32768
#define NN   1024

// [b][{kx0,kx1,kx2,p}][n]
__device__ __align__(256) float g_tab[4][4][NN];

__device__ __forceinline__ u64 pk2(float lo, float hi) {
    u64 r; asm("mov.b64 %0, {%1, %2};" : "=l"(r) : "f"(lo), "f"(hi)); return r;
}
__device__ __forceinline__ void upk2(u64 v, float& lo, float& hi) {
    asm("mov.b64 {%0, %1}, %2;" : "=f"(lo), "=f"(hi) : "l"(v));
}
__device__ __forceinline__ u64 fma2(u64 a, u64 b, u64 c) {
    u64 d; asm("fma.rn.f32x2 %0, %1, %2, %3;" : "=l"(d) : "l"(a), "l"(b), "l"(c)); return d;
}
__device__ __forceinline__ u64 mul2(u64 a, u64 b) {
    u64 d; asm("mul.rn.f32x2 %0, %1, %2;" : "=l"(d) : "l"(a), "l"(b)); return d;
}
__device__ __forceinline__ u64 add2(u64 a, u64 b) {
    u64 d; asm("add.rn.f32x2 %0, %1, %2;" : "=l"(d) : "l"(a), "l"(b)); return d;
}
__device__ __forceinline__ float ex2f(float x) {
    float r; asm("ex2.approx.ftz.f32 %0, %1;" : "=f"(r) : "f"(x)); return r;
}

// ---- prologue: per-(b,n) folded constants -------------------------------
__global__ void pv_pre(const float* __restrict__ xyz, const float* __restrict__ s1) {
    int i = blockIdx.x * blockDim.x + threadIdx.x;   // 0..4095
    if (i >= 4 * NN) return;
    int b = i >> 10, n = i & (NN - 1);
    const float L = 1.4426950408889634f;
    float s1a = fabsf(s1[0]);
    float k = 2.0f * s1a * L;
    float x0 = xyz[b * 3 * NN + 0 * NN + n];
    float x1 = xyz[b * 3 * NN + 1 * NN + n];
    float x2 = xyz[b * 3 * NN + 2 * NN + n];
    g_tab[b][0][n] = k * x0;
    g_tab[b][1][n] = k * x1;
    g_tab[b][2][n] = k * x2;
    g_tab[b][3][n] = -s1a * L * (x0 * x0 + x1 * x1 + x2 * x2);
}

// ---- main: one warp -> 2 voxels x 4 batches = 8 outputs -----------------
__global__ void __launch_bounds__(256, 1) pv_main(
    const float* __restrict__ grid,
    const float* __restrict__ s1,
    const float* __restrict__ s2,
    float* __restrict__ out)
{
    int lane = threadIdx.x & 31;
    int warp = blockIdx.x * (blockDim.x >> 5) + (threadIdx.x >> 5);
    int vox0 = warp * 2;

    const float L = 1.4426950408889634f;
    float s1a = fabsf(s1[0]);
    float s2a = fabsf(s2[0]);
    float A = -s1a * L;

    // per-voxel grid values (broadcast-packed) and w scalars
    u64 G[2][3], W[2];
    #pragma unroll
    for (int v = 0; v < 2; v++) {
        int vx = vox0 + v;
        float g0 = grid[vx];
        float g1 = grid[VOXN + vx];
        float g2 = grid[2 * VOXN + vx];
        G[v][0] = pk2(g0, g0);
        G[v][1] = pk2(g1, g1);
        G[v][2] = pk2(g2, g2);
        float w = s2a * ex2f(A * (g0 * g0 + g1 * g1 + g2 * g2));
        W[v] = pk2(w, w);
    }

    // Taylor deg-7 coefficients for e^x on [0,1] (Horner, high -> low)
    const u64 C7 = pk2(1.9841270e-4f, 1.9841270e-4f);
    const u64 C6 = pk2(1.3888889e-3f, 1.3888889e-3f);
    const u64 C5 = pk2(8.3333333e-3f, 8.3333333e-3f);
    const u64 C4 = pk2(4.1666667e-2f, 4.1666667e-2f);
    const u64 C3 = pk2(0.16666667f, 0.16666667f);
    const u64 C2 = pk2(0.5f, 0.5f);
    const u64 C1 = pk2(1.0f, 1.0f);
    const u64 C0 = pk2(1.0f, 1.0f);

    u64 S[8];
    float m0[8], m1[8];
    #pragma unroll
    for (int o = 0; o < 8; o++) { S[o] = pk2(0.f, 0.f); m0[o] = 0.f; m1[o] = 0.f; }

    int base = lane * 2;   // even n index; u64 load = packed {n, n+1}

    #pragma unroll 1
    for (int j = 0; j < 16; j++) {
        u64 X[4][4];
        #pragma unroll
        for (int b = 0; b < 4; b++) {
            #pragma unroll
            for (int a = 0; a < 4; a++) {
                X[b][a] = *reinterpret_cast<const u64*>(&g_tab[b][a][base]);
            }
        }
        #pragma unroll
        for (int v = 0; v < 2; v++) {
            #pragma unroll
            for (int b = 0; b < 4; b++) {
                int o = v * 4 + b;
                // a = p_n + kX0*g0 + kX1*g1 + kX2*g2 (packed over 2 n's)
                u64 acc = fma2(X[b][0], G[v][0], X[b][3]);
                acc = fma2(X[b][1], G[v][1], acc);
                acc = fma2(X[b][2], G[v][2], acc);
                float alo, ahi; upk2(acc, alo, ahi);
                float elo = ex2f(alo);
                float ehi = ex2f(ahi);
                u64 vv = mul2(pk2(elo, ehi), W[v]);      // v in [0,1]
                // E = exp(v) via Taylor-7 (packed)
                u64 p = fma2(C7, vv, C6);
                p = fma2(p, vv, C5);
                p = fma2(p, vv, C4);
                p = fma2(p, vv, C3);
                p = fma2(p, vv, C2);
                p = fma2(p, vv, C1);
                p = fma2(p, vv, C0);
                S[o] = add2(S[o], p);
                // top-2 tracking on E (monotone in v) — ALU pipe FMNMX
                float plo, phi; upk2(p, plo, phi);
                m1[o] = fmaxf(m1[o], fminf(m0[o], plo));
                m0[o] = fmaxf(m0[o], plo);
                m1[o] = fmaxf(m1[o], fminf(m0[o], phi));
                m0[o] = fmaxf(m0[o], phi);
            }
        }
        base += 64;
    }

    // cross-lane reduction per output (butterfly merge of top-2 + sum)
    float res = 0.f;
    #pragma unroll
    for (int o = 0; o < 8; o++) {
        float slo, shi; upk2(S[o], slo, shi);
        float Sf = slo + shi;
        float M0 = m0[o], M1 = m1[o];
        #pragma unroll
        for (int off = 16; off; off >>= 1) {
            float o0 = __shfl_xor_sync(0xffffffffu, M0, off);
            float o1 = __shfl_xor_sync(0xffffffffu, M1, off);
            float os = __shfl_xor_sync(0xffffffffu, Sf, off);
            M1 = fmaxf(fmaxf(M1, o1), fminf(M0, o0));
            M0 = fmaxf(M0, o0);
            Sf += os;
        }
        if (lane == o) res = (M0 - M1) / Sf;
    }
    if (lane < 8) {
        int v = lane >> 2, b = lane & 3;
        out[b * VOXN + vox0 + v] = res;
    }
}

extern "C" void kernel_launch(void* const* d_in, const int* in_sizes, int n_in,
                              void* d_out, int out_size) {
    // robust input identification by element count
    const float* xyz = nullptr; const float* grid = nullptr;
    const float* s1 = nullptr;  const float* s2 = nullptr;
    for (int i = 0; i < n_in; i++) {
        if (in_sizes[i] == 4 * 3 * NN)      xyz = (const float*)d_in[i];
        else if (in_sizes[i] == 3 * VOXN)   grid = (const float*)d_in[i];
        else if (in_sizes[i] == 1) { if (!s1) s1 = (const float*)d_in[i]; else s2 = (const float*)d_in[i]; }
    }
    float* out = (float*)d_out;

    pv_pre<<<16, 256>>>(xyz, s1);
    // 131072 outputs, 8 per warp -> 16384 warps -> 2048 blocks of 8 warps
    pv_main<<<2048, 256>>>(grid, s1, s2, out);
}

// round 2
// speedup vs baseline: 1.2638x; 1.2638x over previous
#include <cuda_runtime.h>
#include <math.h>

// P2V: out[b,vox] = top2-margin of softmax_n( |s2| * exp(-|s1| * |xyz[b,:,n]-grid[:,vox]|^2) )
// margin = (exp(v0)-exp(v1)) / sum_n exp(v_n),  v_n = |s2|*exp(-|s1|*dist_n) in (0,1]
//
// v_n = W_vox * 2^( kx0*g0 + kx1*g1 + kx2*g2 + p_n )   (one MUFU ex2 per pair)
//   kxc = 2*s1*log2e*x_c,  p_n = -s1*log2e*|x_n|^2     (per (b,n) table, interleaved pairs)
//   W   = s2 * 2^(-s1*log2e*|g|^2)                     (per-voxel table {g0,g1,g2,w})
// exp(v) for the softmax sum via deg-4 minimax poly P(v)=v*Q(v)+c0 on [0,1] (err ~3e-5),
// accumulated as S = fma(Q, v, S); +1024*c0 added once. Top-2 tracked on v (monotone),
// exact __expf applied to the final two values only.

typedef unsigned long long u64;

#define VOXN 32768
#define NN   1024

// [b][pair][ kx0_n, kx0_n1, kx1_n, kx1_n1, kx2_n, kx2_n1, p_n, p_n1 ]
__device__ __align__(256) float  g_tab2[4][512][8];
__device__ __align__(16)  float4 g_vox[VOXN];

__device__ __forceinline__ u64 pk2(float lo, float hi) {
    u64 r; asm("mov.b64 %0, {%1, %2};" : "=l"(r) : "f"(lo), "f"(hi)); return r;
}
__device__ __forceinline__ void upk2(u64 v, float& lo, float& hi) {
    asm("mov.b64 {%0, %1}, %2;" : "=f"(lo), "=f"(hi) : "l"(v));
}
__device__ __forceinline__ u64 fma2(u64 a, u64 b, u64 c) {
    u64 d; asm("fma.rn.f32x2 %0, %1, %2, %3;" : "=l"(d) : "l"(a), "l"(b), "l"(c)); return d;
}
__device__ __forceinline__ u64 mul2(u64 a, u64 b) {
    u64 d; asm("mul.rn.f32x2 %0, %1, %2;" : "=l"(d) : "l"(a), "l"(b)); return d;
}
__device__ __forceinline__ float ex2f(float x) {
    float r; asm("ex2.approx.ftz.f32 %0, %1;" : "=f"(r) : "f"(x)); return r;
}

// deg-4 minimax (Chebyshev) for e^x on [0,1]: P(x) = ((((c4 x + c3)x + c2)x + c1)x + c0
#define C4F 0.0695600f
#define C3F 0.1400096f
#define C2F 0.5099252f
#define C1F 0.9987378f
#define C0F 1.0000236f

// ---- prologue 1: per-(b,n) folded constants, interleaved pair layout ----
__global__ void pv_pre(const float* __restrict__ xyz, const float* __restrict__ s1) {
    int i = blockIdx.x * blockDim.x + threadIdx.x;   // 0..4095
    if (i >= 4 * NN) return;
    int b = i >> 10, n = i & (NN - 1);
    const float L = 1.4426950408889634f;
    float s1a = fabsf(s1[0]);
    float k = 2.0f * s1a * L;
    float x0 = xyz[b * 3 * NN + 0 * NN + n];
    float x1 = xyz[b * 3 * NN + 1 * NN + n];
    float x2 = xyz[b * 3 * NN + 2 * NN + n];
    int pr = n >> 1, h = n & 1;
    g_tab2[b][pr][0 + h] = k * x0;
    g_tab2[b][pr][2 + h] = k * x1;
    g_tab2[b][pr][4 + h] = k * x2;
    g_tab2[b][pr][6 + h] = -s1a * L * (x0 * x0 + x1 * x1 + x2 * x2);
}

// ---- prologue 2: per-voxel {g0,g1,g2,w} ----
__global__ void pv_vox(const float* __restrict__ grid,
                       const float* __restrict__ s1,
                       const float* __restrict__ s2) {
    int vx = blockIdx.x * blockDim.x + threadIdx.x;
    if (vx >= VOXN) return;
    const float L = 1.4426950408889634f;
    float g0 = grid[vx];
    float g1 = grid[VOXN + vx];
    float g2 = grid[2 * VOXN + vx];
    float w = fabsf(s2[0]) * exp2f(-fabsf(s1[0]) * L * (g0 * g0 + g1 * g1 + g2 * g2));
    g_vox[vx] = make_float4(g0, g1, g2, w);
}

// ---- main: one warp -> 4 voxels x 2 batches = 8 outputs --------------------
__global__ void __launch_bounds__(128, 4) pv_main(float* __restrict__ out)
{
    int lane = threadIdx.x & 31;
    int warp = blockIdx.x * 4 + (threadIdx.x >> 5);
    int vg = warp >> 1;          // voxel group (4 voxels)
    int bh = warp & 1;           // batch half: b in {2bh, 2bh+1}
    int vox0 = vg * 4;

    // per-voxel broadcast constants
    u64 G[4][3], W[4];
    #pragma unroll
    for (int v = 0; v < 4; v++) {
        float4 gv = g_vox[vox0 + v];
        G[v][0] = pk2(gv.x, gv.x);
        G[v][1] = pk2(gv.y, gv.y);
        G[v][2] = pk2(gv.z, gv.z);
        W[v]    = pk2(gv.w, gv.w);
    }

    const u64 Cq3 = pk2(C4F, C4F);
    const u64 Cq2 = pk2(C3F, C3F);
    const u64 Cq1 = pk2(C2F, C2F);
    const u64 Cq0 = pk2(C1F, C1F);

    u64 S[8];
    float m0[8], m1[8];
    #pragma unroll
    for (int o = 0; o < 8; o++) { S[o] = 0ull; m0[o] = 0.f; m1[o] = 0.f; }

    // table pointer: u64 units. per-b stride = 512 pairs * 4 u64 = 2048.
    // lane starts at pair=lane; j-stride = 32 pairs = 128 u64.
    const u64* tp = reinterpret_cast<const u64*>(g_tab2) + (u64)(2 * bh) * 2048 + lane * 4;

    u64 A0[4], A1[4], B0[4], B1[4];
    #pragma unroll
    for (int a = 0; a < 4; a++) { A0[a] = tp[a]; A1[a] = tp[2048 + a]; }

    #pragma unroll 1
    for (int j = 0; j < 16; j += 2) {
        // prefetch pair-block for j+1
        const u64* tq = tp + 128;
        #pragma unroll
        for (int a = 0; a < 4; a++) { B0[a] = tq[a]; B1[a] = tq[2048 + a]; }

        // compute on A (j)
        #pragma unroll
        for (int v = 0; v < 4; v++) {
            #pragma unroll
            for (int bi = 0; bi < 2; bi++) {
                const u64* X = bi ? A1 : A0;
                int o = v * 2 + bi;
                u64 acc = fma2(X[0], G[v][0], X[3]);
                acc = fma2(X[1], G[v][1], acc);
                acc = fma2(X[2], G[v][2], acc);
                float alo, ahi; upk2(acc, alo, ahi);
                u64 vv = mul2(pk2(ex2f(alo), ex2f(ahi)), W[v]);
                u64 q = fma2(Cq3, vv, Cq2);
                q = fma2(q, vv, Cq1);
                q = fma2(q, vv, Cq0);
                S[o] = fma2(q, vv, S[o]);
                float vlo, vhi; upk2(vv, vlo, vhi);
                m1[o] = fmaxf(m1[o], fminf(m0[o], vlo));
                m0[o] = fmaxf(m0[o], vlo);
                m1[o] = fmaxf(m1[o], fminf(m0[o], vhi));
                m0[o] = fmaxf(m0[o], vhi);
            }
        }

        tp += 256;
        // prefetch pair-block for j+2 (guarded)
        if (j + 2 < 16) {
            #pragma unroll
            for (int a = 0; a < 4; a++) { A0[a] = tp[a]; A1[a] = tp[2048 + a]; }
        }

        // compute on B (j+1)
        #pragma unroll
        for (int v = 0; v < 4; v++) {
            #pragma unroll
            for (int bi = 0; bi < 2; bi++) {
                const u64* X = bi ? B1 : B0;
                int o = v * 2 + bi;
                u64 acc = fma2(X[0], G[v][0], X[3]);
                acc = fma2(X[1], G[v][1], acc);
                acc = fma2(X[2], G[v][2], acc);
                float alo, ahi; upk2(acc, alo, ahi);
                u64 vv = mul2(pk2(ex2f(alo), ex2f(ahi)), W[v]);
                u64 q = fma2(Cq3, vv, Cq2);
                q = fma2(q, vv, Cq1);
                q = fma2(q, vv, Cq0);
                S[o] = fma2(q, vv, S[o]);
                float vlo, vhi; upk2(vv, vlo, vhi);
                m1[o] = fmaxf(m1[o], fminf(m0[o], vlo));
                m0[o] = fmaxf(m0[o], vlo);
                m1[o] = fmaxf(m1[o], fminf(m0[o], vhi));
                m0[o] = fmaxf(m0[o], vhi);
            }
        }
    }

    // cross-lane reduction per output (butterfly merge of top-2 + sum)
    float res = 0.f;
    #pragma unroll
    for (int o = 0; o < 8; o++) {
        float slo, shi; upk2(S[o], slo, shi);
        float Sf = slo + shi;
        float M0 = m0[o], M1 = m1[o];
        #pragma unroll
        for (int off = 16; off; off >>= 1) {
            float o0 = __shfl_xor_sync(0xffffffffu, M0, off);
            float o1 = __shfl_xor_sync(0xffffffffu, M1, off);
            float os = __shfl_xor_sync(0xffffffffu, Sf, off);
            M1 = fmaxf(fmaxf(M1, o1), fminf(M0, o0));
            M0 = fmaxf(M0, o0);
            Sf += os;
        }
        if (lane == o)
            res = (__expf(M0) - __expf(M1)) / (Sf + 1024.0f * C0F);
    }
    if (lane < 8) {
        int v = lane >> 1, bi = lane & 1;
        out[(2 * bh + bi) * VOXN + vox0 + v] = res;
    }
}

extern "C" void kernel_launch(void* const* d_in, const int* in_sizes, int n_in,
                              void* d_out, int out_size) {
    const float* xyz = nullptr; const float* grid = nullptr;
    const float* s1 = nullptr;  const float* s2 = nullptr;
    for (int i = 0; i < n_in; i++) {
        if (in_sizes[i] == 4 * 3 * NN)      xyz = (const float*)d_in[i];
        else if (in_sizes[i] == 3 * VOXN)   grid = (const float*)d_in[i];
        else if (in_sizes[i] == 1) { if (!s1) s1 = (const float*)d_in[i]; else s2 = (const float*)d_in[i]; }
    }
    float* out = (float*)d_out;

    pv_pre<<<16, 256>>>(xyz, s1);
    pv_vox<<<128, 256>>>(grid, s1, s2);
    // 131072 outputs, 8 per warp -> 16384 warps -> 4096 blocks of 4 warps
    pv_main<<<4096, 128>>>(out);
}